// round 5
// baseline (speedup 1.0000x reference)
#include <cuda_runtime.h>
#include <cuda_bf16.h>
#include <math.h>

// ---------------- problem constants ----------------
#define DIMX     512
#define INTER    64
#define NSH      2
#define NROUTED  64
#define NEXP     66
#define TOPK     6
#define KSLOT    8
#define NTOK     1024
#define NSLOT    (NTOK * KSLOT)
#define TILE_M   32
#define MAXTILES 320

typedef unsigned long long u64;

// ---------------- packed f32x2 helpers ----------------
__device__ __forceinline__ u64 ffma2(u64 a, u64 b, u64 c) {
    u64 d; asm("fma.rn.f32x2 %0, %1, %2, %3;" : "=l"(d) : "l"(a), "l"(b), "l"(c)); return d;
}
__device__ __forceinline__ u64 fmul2(u64 a, u64 b) {
    u64 d; asm("mul.rn.f32x2 %0, %1, %2;" : "=l"(d) : "l"(a), "l"(b)); return d;
}
__device__ __forceinline__ u64 fpack(float lo, float hi) {
    u64 d; asm("mov.b64 %0, {%1, %2};" : "=l"(d) : "f"(lo), "f"(hi)); return d;
}
__device__ __forceinline__ u64 fdup(float s) { return fpack(s, s); }
__device__ __forceinline__ void funpack(u64 v, float& a, float& b) {
    asm("mov.b64 {%0, %1}, %2;" : "=f"(a), "=f"(b) : "l"(v));
}

// ---------------- cp.async helpers ----------------
__device__ __forceinline__ void cp_async16(void* smem_dst, const void* gmem_src) {
    unsigned s = (unsigned)__cvta_generic_to_shared(smem_dst);
    asm volatile("cp.async.cg.shared.global [%0], [%1], 16;\n" :: "r"(s), "l"(gmem_src));
}
__device__ __forceinline__ void cp_commit() { asm volatile("cp.async.commit_group;"); }
template<int N> __device__ __forceinline__ void cp_wait() {
    asm volatile("cp.async.wait_group %0;" :: "n"(N));
}

// ---------------- device scratch ----------------
__device__ int   g_eidx[NSLOT];
__device__ float g_wt[NSLOT];
__device__ int   g_pos[NSLOT];         // within-expert rank per slot
__device__ int   g_counts[NEXP];
__device__ int   g_offsets[NEXP + 1];
__device__ int   g_perm[NSLOT];
__device__ int4  g_tiles[MAXTILES];
__device__ int   g_ntiles;
__device__ float g_slot_out[(size_t)NSLOT * DIMX];

// ---------------- kernel 0: zero counters ----------------
__global__ void zero_kernel() {
    int t = threadIdx.x;
    if (t < NEXP) g_counts[t] = 0;
}

// ---------------- kernel 1: gate ----------------
__global__ __launch_bounds__(256) void gate_kernel(
    const float* __restrict__ x, const float* __restrict__ gw,
    const float* __restrict__ bias)
{
    __shared__ float Xs[32][32];
    __shared__ float Gs[32][65];
    __shared__ float S[32][66];

    int tid  = threadIdx.x;
    int tok0 = blockIdx.x * 32;
    int tg   = tid >> 5;
    int lane = tid & 31;

    float acc[4][2] = {};

    for (int k0 = 0; k0 < DIMX; k0 += 32) {
        {
            int r = tid >> 3;
            int c = (tid & 7) * 4;
            float4 v = *reinterpret_cast<const float4*>(&x[(size_t)(tok0 + r) * DIMX + k0 + c]);
            Xs[r][c] = v.x; Xs[r][c+1] = v.y; Xs[r][c+2] = v.z; Xs[r][c+3] = v.w;
        }
        {
            int e  = tid >> 2;
            int kk = (tid & 3) * 8;
            float4 a = *reinterpret_cast<const float4*>(&gw[(size_t)e * DIMX + k0 + kk]);
            float4 b = *reinterpret_cast<const float4*>(&gw[(size_t)e * DIMX + k0 + kk + 4]);
            Gs[kk+0][e] = a.x; Gs[kk+1][e] = a.y; Gs[kk+2][e] = a.z; Gs[kk+3][e] = a.w;
            Gs[kk+4][e] = b.x; Gs[kk+5][e] = b.y; Gs[kk+6][e] = b.z; Gs[kk+7][e] = b.w;
        }
        __syncthreads();
        #pragma unroll
        for (int kk = 0; kk < 32; kk++) {
            float g0 = Gs[kk][lane], g1 = Gs[kk][lane + 32];
            #pragma unroll
            for (int i = 0; i < 4; i++) {
                float xv = Xs[tg * 4 + i][kk];
                acc[i][0] = fmaf(xv, g0, acc[i][0]);
                acc[i][1] = fmaf(xv, g1, acc[i][1]);
            }
        }
        __syncthreads();
    }
    #pragma unroll
    for (int i = 0; i < 4; i++) {
        S[tg * 4 + i][lane]      = acc[i][0];
        S[tg * 4 + i][lane + 32] = acc[i][1];
    }
    __syncthreads();

    float b0 = bias[lane], b1 = bias[lane + 32];
    for (int i = 0; i < 4; i++) {
        int t = tg * 4 + i;
        float s0 = S[t][lane], s1 = S[t][lane + 32];
        float mx = fmaxf(s0, s1);
        #pragma unroll
        for (int o = 16; o > 0; o >>= 1) mx = fmaxf(mx, __shfl_xor_sync(0xffffffffu, mx, o));
        float e0 = expf(s0 - mx), e1 = expf(s1 - mx);
        float z = e0 + e1;
        #pragma unroll
        for (int o = 16; o > 0; o >>= 1) z += __shfl_xor_sync(0xffffffffu, z, o);
        float inv = 1.0f / z;
        float p0 = e0 * inv, p1 = e1 * inv;
        float k0v = p0 + b0, k1v = p1 + b1;
        int gt = tok0 + t;
        for (int r = 0; r < TOPK; r++) {
            float key, pv; int idx;
            if (k0v >= k1v) { key = k0v; pv = p0; idx = lane; }
            else            { key = k1v; pv = p1; idx = lane + 32; }
            #pragma unroll
            for (int o = 16; o > 0; o >>= 1) {
                float ok = __shfl_xor_sync(0xffffffffu, key, o);
                float op = __shfl_xor_sync(0xffffffffu, pv,  o);
                int   oi = __shfl_xor_sync(0xffffffffu, idx, o);
                if (ok > key || (ok == key && oi < idx)) { key = ok; pv = op; idx = oi; }
            }
            if (lane == 0) {
                int slot = gt * KSLOT + NSH + r;
                g_eidx[slot] = idx + NSH;
                g_wt  [slot] = pv;
                g_pos [slot] = atomicAdd(&g_counts[idx + NSH], 1);
            }
            if (idx == lane)           k0v = -INFINITY;
            else if (idx == lane + 32) k1v = -INFINITY;
        }
        if (lane < NSH) {
            int slot = gt * KSLOT + lane;
            g_eidx[slot] = lane;
            g_wt  [slot] = 1.0f;
            g_pos [slot] = gt;
        }
    }
}

// ---------------- kernel 2: scan + tile build ----------------
__global__ void scan_kernel() {
    __shared__ int cnt[NEXP];
    int tid = threadIdx.x;
    if (tid < NEXP) cnt[tid] = (tid < NSH) ? NTOK : g_counts[tid];
    __syncthreads();
    if (tid == 0) {
        int off = 0, nt = 0;
        for (int e = 0; e < NEXP; e++) {
            g_offsets[e] = off;
            int c = cnt[e];
            for (int j = 0; j < c; j += TILE_M) {
                g_tiles[nt] = make_int4(e, off + j, min(TILE_M, c - j), 0);
                nt++;
            }
            off += c;
        }
        g_offsets[NEXP] = off;
        g_ntiles = nt;
    }
}

// ---------------- kernel 3: scatter (atomic-free) ----------------
__global__ void scatter_kernel() {
    int i = blockIdx.x * 256 + threadIdx.x;
    if (i >= NSLOT) return;
    int e = g_eidx[i];
    g_perm[g_offsets[e] + g_pos[i]] = i;
}

// ---------------- kernel 4: grouped expert FFN (cp.async pipelined, FFMA2) ----------------
// block = 128 threads (4 warps). warp w owns tokens [8w, 8w+8) as 4 token-pairs.
// lane owns j-pair (2*lane, 2*lane+1) in h-stage / d-pair in W2-stage.
__global__ __launch_bounds__(128, 4) void ffn_kernel(
    const float* __restrict__ x,  const float* __restrict__ w1,
    const float* __restrict__ w2, const float* __restrict__ w3)
{
    extern __shared__ float sm[];
    float* Wbuf = sm;           // 8192 floats: two 4096-float halves
    float* Xbuf = sm + 8192;    // 2304 floats: two [32k][36] transposed X slices
    float* Gt   = sm + 8192;    // alias (used after h-stage): [64 j][36 tok]
    __shared__ int   toks[TILE_M];
    __shared__ float wts[TILE_M];
    __shared__ int   slots[TILE_M];

    int bid = blockIdx.x;
    if (bid >= g_ntiles) return;
    int4 tl = g_tiles[bid];
    int e = tl.x, p0 = tl.y, m = tl.z;

    int tid  = threadIdx.x;
    int wid  = tid >> 5;
    int lane = tid & 31;

    if (tid < TILE_M) {
        int i = (tid < m) ? g_perm[p0 + tid] : g_perm[p0];
        slots[tid] = i;
        toks[tid]  = i >> 3;
        wts[tid]   = g_wt[i];
    }

    const float* w1e = w1 + (size_t)e * DIMX * INTER;
    const float* w3e = w3 + (size_t)e * DIMX * INTER;
    const float* w2e = w2 + (size_t)e * INTER * DIMX;

    // prefetch W slice 0 into half 0 (single group, every address written once)
    {
        float* dst = Wbuf;
        #pragma unroll
        for (int q = 0; q < 4; q++) {
            cp_async16(dst + q*512 + tid*4,        w1e + q*512 + tid*4);
            cp_async16(dst + 2048 + q*512 + tid*4, w3e + q*512 + tid*4);
        }
        cp_commit();
    }
    __syncthreads();   // toks/slots/wts visible

    // X slice 0 -> registers
    int xt = tid & 31;          // token
    int xc = tid >> 5;          // col group 0..3
    float4 xr0, xr1;
    {
        const float* xrow = &x[(size_t)toks[xt] * DIMX];
        xr0 = *reinterpret_cast<const float4*>(&xrow[xc * 4]);
        xr1 = *reinterpret_cast<const float4*>(&xrow[(xc + 4) * 4]);
    }

    u64 h1[4][2] = {}, h3[4][2] = {};

    for (int kb = 0; kb < 16; kb++) {
        __syncthreads();   // compute kb-1 done by all: Xbuf[kb&1] & Wbuf[(kb+1)&1] free
        // store current X slice (from regs) transposed
        {
            float* Xc = Xbuf + (kb & 1) * 1152;
            Xc[(xc*4+0)*36 + xt] = xr0.x; Xc[(xc*4+1)*36 + xt] = xr0.y;
            Xc[(xc*4+2)*36 + xt] = xr0.z; Xc[(xc*4+3)*36 + xt] = xr0.w;
            Xc[((xc+4)*4+0)*36 + xt] = xr1.x; Xc[((xc+4)*4+1)*36 + xt] = xr1.y;
            Xc[((xc+4)*4+2)*36 + xt] = xr1.z; Xc[((xc+4)*4+3)*36 + xt] = xr1.w;
        }
        if (kb + 1 < 16) {
            float* dst = Wbuf + ((kb + 1) & 1) * 4096;
            const float* s1 = w1e + (kb + 1) * 2048;
            const float* s3 = w3e + (kb + 1) * 2048;
            #pragma unroll
            for (int q = 0; q < 4; q++) {
                cp_async16(dst + q*512 + tid*4,        s1 + q*512 + tid*4);
                cp_async16(dst + 2048 + q*512 + tid*4, s3 + q*512 + tid*4);
            }
            cp_commit();
            const float* xrow = &x[(size_t)toks[xt] * DIMX + (kb + 1) * 32];
            xr0 = *reinterpret_cast<const float4*>(&xrow[xc * 4]);
            xr1 = *reinterpret_cast<const float4*>(&xrow[(xc + 4) * 4]);
            cp_wait<1>();
        } else {
            // prefetch W2 slice db=0 into half0 (last read of half0 was compute kb=14)
            float* dst = Wbuf;
            #pragma unroll
            for (int q = 0; q < 8; q++) {
                int id = tid + q * 128;
                int j = id >> 4, c = (id & 15) * 4;
                cp_async16(dst + j*64 + c, w2e + (size_t)j * DIMX + c);
            }
            cp_commit();
            cp_wait<1>();   // newest = W2-db0 pending; W slice 15 complete
        }
        __syncthreads();   // X STS + W slice kb visible

        const float* W1h = Wbuf + (kb & 1) * 4096;
        const float* W3h = W1h + 2048;
        const float* Xc  = Xbuf + (kb & 1) * 1152;
        #pragma unroll
        for (int kk = 0; kk < 32; kk++) {
            u64 w1p = *reinterpret_cast<const u64*>(&W1h[kk*64 + 2*lane]);
            u64 w3p = *reinterpret_cast<const u64*>(&W3h[kk*64 + 2*lane]);
            float a0, a1, b0, b1;
            funpack(w1p, a0, a1); funpack(w3p, b0, b1);
            u64 d1a = fdup(a0), d1b = fdup(a1), d3a = fdup(b0), d3b = fdup(b1);
            float4 xA = *reinterpret_cast<const float4*>(&Xc[kk*36 + 8*wid]);
            float4 xB = *reinterpret_cast<const float4*>(&Xc[kk*36 + 8*wid + 4]);
            u64 pA0 = fpack(xA.x, xA.y), pA1 = fpack(xA.z, xA.w);
            u64 pB0 = fpack(xB.x, xB.y), pB1 = fpack(xB.z, xB.w);
            h1[0][0] = ffma2(pA0, d1a, h1[0][0]); h1[0][1] = ffma2(pA0, d1b, h1[0][1]);
            h1[1][0] = ffma2(pA1, d1a, h1[1][0]); h1[1][1] = ffma2(pA1, d1b, h1[1][1]);
            h1[2][0] = ffma2(pB0, d1a, h1[2][0]); h1[2][1] = ffma2(pB0, d1b, h1[2][1]);
            h1[3][0] = ffma2(pB1, d1a, h1[3][0]); h1[3][1] = ffma2(pB1, d1b, h1[3][1]);
            h3[0][0] = ffma2(pA0, d3a, h3[0][0]); h3[0][1] = ffma2(pA0, d3b, h3[0][1]);
            h3[1][0] = ffma2(pA1, d3a, h3[1][0]); h3[1][1] = ffma2(pA1, d3b, h3[1][1]);
            h3[2][0] = ffma2(pB0, d3a, h3[2][0]); h3[2][1] = ffma2(pB0, d3b, h3[2][1]);
            h3[3][0] = ffma2(pB1, d3a, h3[3][0]); h3[3][1] = ffma2(pB1, d3b, h3[3][1]);
        }
    }

    __syncthreads();   // all compute done before Gt (aliases Xbuf) is written

    // epilogue: silu(h1)*h3 -> Gt[j][tok]
    #pragma unroll
    for (int p = 0; p < 4; p++) {
        #pragma unroll
        for (int jc = 0; jc < 2; jc++) {
            float v0, v1, g0, g1;
            funpack(h1[p][jc], v0, v1);
            funpack(h3[p][jc], g0, g1);
            float s0 = (v0 / (1.0f + expf(-v0))) * g0;
            float s1 = (v1 / (1.0f + expf(-v1))) * g1;
            int j = 2*lane + jc;
            *reinterpret_cast<u64*>(&Gt[j*36 + 8*wid + 2*p]) = fpack(s0, s1);
        }
    }

    // ---- W2 stage ----
    for (int db = 0; db < 8; db++) {
        __syncthreads();   // prev compute done; for db=0 also publishes Gt
        if (db + 1 < 8) {
            float* dst = Wbuf + ((db + 1) & 1) * 4096;
            #pragma unroll
            for (int q = 0; q < 8; q++) {
                int id = tid + q * 128;
                int j = id >> 4, c = (id & 15) * 4;
                cp_async16(dst + j*64 + c, w2e + (size_t)j * DIMX + (db + 1) * 64 + c);
            }
            cp_commit();
            cp_wait<1>();
        } else {
            cp_wait<0>();
        }
        __syncthreads();

        const float* W2h = Wbuf + (db & 1) * 4096;
        u64 o[4][2] = {};
        #pragma unroll 16
        for (int j = 0; j < 64; j++) {
            u64 w2p = *reinterpret_cast<const u64*>(&W2h[j*64 + 2*lane]);
            float b0, b1; funpack(w2p, b0, b1);
            u64 da = fdup(b0), dbv = fdup(b1);
            float4 gA = *reinterpret_cast<const float4*>(&Gt[j*36 + 8*wid]);
            float4 gB = *reinterpret_cast<const float4*>(&Gt[j*36 + 8*wid + 4]);
            u64 g0 = fpack(gA.x, gA.y), g1 = fpack(gA.z, gA.w);
            u64 g2 = fpack(gB.x, gB.y), g3 = fpack(gB.z, gB.w);
            o[0][0] = ffma2(g0, da, o[0][0]); o[0][1] = ffma2(g0, dbv, o[0][1]);
            o[1][0] = ffma2(g1, da, o[1][0]); o[1][1] = ffma2(g1, dbv, o[1][1]);
            o[2][0] = ffma2(g2, da, o[2][0]); o[2][1] = ffma2(g2, dbv, o[2][1]);
            o[3][0] = ffma2(g3, da, o[3][0]); o[3][1] = ffma2(g3, dbv, o[3][1]);
        }
        // o[p][dc] lanes = token pair (8wid+2p, 8wid+2p+1) at d = 2*lane+dc
        #pragma unroll
        for (int p = 0; p < 4; p++) {
            int t0 = 8*wid + 2*p, t1 = t0 + 1;
            float x00, x10, x01, x11;
            funpack(o[p][0], x00, x10);
            funpack(o[p][1], x01, x11);
            if (t0 < m) {
                u64 v = fmul2(fpack(x00, x01), fdup(wts[t0]));
                *reinterpret_cast<u64*>(
                    &g_slot_out[(size_t)slots[t0]*DIMX + db*64 + 2*lane]) = v;
            }
            if (t1 < m) {
                u64 v = fmul2(fpack(x10, x11), fdup(wts[t1]));
                *reinterpret_cast<u64*>(
                    &g_slot_out[(size_t)slots[t1]*DIMX + db*64 + 2*lane]) = v;
            }
        }
    }
}

// ---------------- kernel 5: combine ----------------
__global__ void combine_kernel(float* __restrict__ out) {
    int i = blockIdx.x * 256 + threadIdx.x;
    if (i >= NTOK * DIMX / 4) return;
    int t = i >> 7;
    int d4 = i & (DIMX/4 - 1);
    float4 s = make_float4(0.f, 0.f, 0.f, 0.f);
    #pragma unroll
    for (int sl = 0; sl < KSLOT; sl++) {
        const float4* p = reinterpret_cast<const float4*>(
            &g_slot_out[((size_t)(t * KSLOT + sl)) * DIMX]);
        float4 v = p[d4];
        s.x += v.x; s.y += v.y; s.z += v.z; s.w += v.w;
    }
    reinterpret_cast<float4*>(out)[i] = s;
}

// ---------------- launch ----------------
extern "C" void kernel_launch(void* const* d_in, const int* in_sizes, int n_in,
                              void* d_out, int out_size) {
    const float* x  = (const float*)d_in[0];
    const float* gw = (const float*)d_in[1];
    const float* gb = (const float*)d_in[2];
    const float* w1 = (const float*)d_in[3];
    const float* w2 = (const float*)d_in[4];
    const float* w3 = (const float*)d_in[5];
    float* out = (float*)d_out;

    const int ffn_smem = (8192 + 2304) * 4;   // 41984 B

    zero_kernel<<<1, 128>>>();
    gate_kernel<<<NTOK / 32, 256>>>(x, gw, gb);
    scan_kernel<<<1, 128>>>();
    scatter_kernel<<<NSLOT / 256, 256>>>();
    ffn_kernel<<<MAXTILES, 128, ffn_smem>>>(x, w1, w2, w3);
    combine_kernel<<<(NTOK * DIMX / 4) / 256, 256>>>(out);
}

// round 8
// speedup vs baseline: 1.3623x; 1.3623x over previous
#include <cuda_runtime.h>
#include <cuda_bf16.h>
#include <math.h>
#include <stdint.h>

// ---------------- problem constants ----------------
#define DIMX     512
#define INTER    64
#define NSH      2
#define NROUTED  64
#define NEXP     66
#define TOPK     6
#define KSLOT    8
#define NTOK     1024
#define NSLOT    (NTOK * KSLOT)
#define TILE_M   32
#define MAXTILES 320

// ---------------- PTX helpers (all sm_80-level, no 'a' features) ----------------
__device__ __forceinline__ uint32_t smem_u32(const void* p) {
    uint32_t a;
    asm("{ .reg .u64 t; cvta.to.shared.u64 t, %1; cvt.u32.u64 %0, t; }" : "=r"(a) : "l"(p));
    return a;
}
__device__ __forceinline__ void cp16(uint32_t sdst, const void* gsrc) {
    asm volatile("cp.async.cg.shared.global [%0], [%1], 16;" :: "r"(sdst), "l"(gsrc));
}
__device__ __forceinline__ void cp_commit() { asm volatile("cp.async.commit_group;"); }
template<int N> __device__ __forceinline__ void cp_wait() {
    asm volatile("cp.async.wait_group %0;" :: "n"(N));
}
__device__ __forceinline__ void ldsm4(uint32_t& r0, uint32_t& r1, uint32_t& r2, uint32_t& r3,
                                      uint32_t addr) {
    asm volatile("ldmatrix.sync.aligned.m8n8.x4.shared.b16 {%0,%1,%2,%3}, [%4];"
                 : "=r"(r0), "=r"(r1), "=r"(r2), "=r"(r3) : "r"(addr));
}
__device__ __forceinline__ void mma_bf16(float* c, const uint32_t* a, const uint32_t* b) {
    asm volatile(
        "mma.sync.aligned.m16n8k16.row.col.f32.bf16.bf16.f32 "
        "{%0,%1,%2,%3}, {%4,%5,%6,%7}, {%8,%9}, {%0,%1,%2,%3};"
        : "+f"(c[0]), "+f"(c[1]), "+f"(c[2]), "+f"(c[3])
        : "r"(a[0]), "r"(a[1]), "r"(a[2]), "r"(a[3]), "r"(b[0]), "r"(b[1]));
}

// ---------------- device scratch ----------------
__device__ int   g_eidx[NSLOT];
__device__ float g_wt[NSLOT];
__device__ int   g_pos[NSLOT];
__device__ int   g_counts[NEXP];
__device__ int   g_offsets[NEXP + 1];
__device__ int   g_perm[NSLOT];
__device__ int4  g_tiles[MAXTILES];
__device__ int   g_ntiles;
__device__ float g_slot_out[(size_t)NSLOT * DIMX];

__device__ __nv_bfloat16 g_xhi[NTOK * DIMX];
__device__ __nv_bfloat16 g_xlo[NTOK * DIMX];
__device__ __nv_bfloat16 g_w13hi[(size_t)NEXP * 128 * DIMX];   // [e][n=128(j1|j3)][k=512]
__device__ __nv_bfloat16 g_w13lo[(size_t)NEXP * 128 * DIMX];
__device__ __nv_bfloat16 g_w2hi[(size_t)NEXP * DIMX * INTER];  // [e][d=512][j=64]
__device__ __nv_bfloat16 g_w2lo[(size_t)NEXP * DIMX * INTER];

// ---------------- kernel 0: zero counters ----------------
__global__ void zero_kernel() {
    int t = threadIdx.x;
    if (t < NEXP) g_counts[t] = 0;
}

// ---------------- kernel 1: gate (proven) ----------------
__global__ __launch_bounds__(256) void gate_kernel(
    const float* __restrict__ x, const float* __restrict__ gw,
    const float* __restrict__ bias)
{
    __shared__ float Xs[32][32];
    __shared__ float Gs[32][65];
    __shared__ float S[32][66];

    int tid  = threadIdx.x;
    int tok0 = blockIdx.x * 32;
    int tg   = tid >> 5;
    int lane = tid & 31;

    float acc[4][2] = {};

    for (int k0 = 0; k0 < DIMX; k0 += 32) {
        {
            int r = tid >> 3;
            int c = (tid & 7) * 4;
            float4 v = *reinterpret_cast<const float4*>(&x[(size_t)(tok0 + r) * DIMX + k0 + c]);
            Xs[r][c] = v.x; Xs[r][c+1] = v.y; Xs[r][c+2] = v.z; Xs[r][c+3] = v.w;
        }
        {
            int e  = tid >> 2;
            int kk = (tid & 3) * 8;
            float4 a = *reinterpret_cast<const float4*>(&gw[(size_t)e * DIMX + k0 + kk]);
            float4 b = *reinterpret_cast<const float4*>(&gw[(size_t)e * DIMX + k0 + kk + 4]);
            Gs[kk+0][e] = a.x; Gs[kk+1][e] = a.y; Gs[kk+2][e] = a.z; Gs[kk+3][e] = a.w;
            Gs[kk+4][e] = b.x; Gs[kk+5][e] = b.y; Gs[kk+6][e] = b.z; Gs[kk+7][e] = b.w;
        }
        __syncthreads();
        #pragma unroll
        for (int kk = 0; kk < 32; kk++) {
            float g0 = Gs[kk][lane], g1 = Gs[kk][lane + 32];
            #pragma unroll
            for (int i = 0; i < 4; i++) {
                float xv = Xs[tg * 4 + i][kk];
                acc[i][0] = fmaf(xv, g0, acc[i][0]);
                acc[i][1] = fmaf(xv, g1, acc[i][1]);
            }
        }
        __syncthreads();
    }
    #pragma unroll
    for (int i = 0; i < 4; i++) {
        S[tg * 4 + i][lane]      = acc[i][0];
        S[tg * 4 + i][lane + 32] = acc[i][1];
    }
    __syncthreads();

    float b0 = bias[lane], b1 = bias[lane + 32];
    for (int i = 0; i < 4; i++) {
        int t = tg * 4 + i;
        float s0 = S[t][lane], s1 = S[t][lane + 32];
        float mx = fmaxf(s0, s1);
        #pragma unroll
        for (int o = 16; o > 0; o >>= 1) mx = fmaxf(mx, __shfl_xor_sync(0xffffffffu, mx, o));
        float e0 = expf(s0 - mx), e1 = expf(s1 - mx);
        float z = e0 + e1;
        #pragma unroll
        for (int o = 16; o > 0; o >>= 1) z += __shfl_xor_sync(0xffffffffu, z, o);
        float inv = 1.0f / z;
        float p0 = e0 * inv, p1 = e1 * inv;
        float k0v = p0 + b0, k1v = p1 + b1;
        int gt = tok0 + t;
        for (int r = 0; r < TOPK; r++) {
            float key, pv; int idx;
            if (k0v >= k1v) { key = k0v; pv = p0; idx = lane; }
            else            { key = k1v; pv = p1; idx = lane + 32; }
            #pragma unroll
            for (int o = 16; o > 0; o >>= 1) {
                float ok = __shfl_xor_sync(0xffffffffu, key, o);
                float op = __shfl_xor_sync(0xffffffffu, pv,  o);
                int   oi = __shfl_xor_sync(0xffffffffu, idx, o);
                if (ok > key || (ok == key && oi < idx)) { key = ok; pv = op; idx = oi; }
            }
            if (lane == 0) {
                int slot = gt * KSLOT + NSH + r;
                g_eidx[slot] = idx + NSH;
                g_wt  [slot] = pv;
                g_pos [slot] = atomicAdd(&g_counts[idx + NSH], 1);
            }
            if (idx == lane)           k0v = -INFINITY;
            else if (idx == lane + 32) k1v = -INFINITY;
        }
        if (lane < NSH) {
            int slot = gt * KSLOT + lane;
            g_eidx[slot] = lane;
            g_wt  [slot] = 1.0f;
            g_pos [slot] = gt;
        }
    }
}

// ---------------- kernel 2: scan + tile build ----------------
__global__ void scan_kernel() {
    __shared__ int cnt[NEXP];
    int tid = threadIdx.x;
    if (tid < NEXP) cnt[tid] = (tid < NSH) ? NTOK : g_counts[tid];
    __syncthreads();
    if (tid == 0) {
        int off = 0, nt = 0;
        for (int e = 0; e < NEXP; e++) {
            g_offsets[e] = off;
            int c = cnt[e];
            for (int j = 0; j < c; j += TILE_M) {
                g_tiles[nt] = make_int4(e, off + j, min(TILE_M, c - j), 0);
                nt++;
            }
            off += c;
        }
        g_offsets[NEXP] = off;
        g_ntiles = nt;
    }
}

// ---------------- kernel 3: scatter (atomic-free) ----------------
__global__ void scatter_kernel() {
    int i = blockIdx.x * 256 + threadIdx.x;
    if (i >= NSLOT) return;
    int e = g_eidx[i];
    g_perm[g_offsets[e] + g_pos[i]] = i;
}

// ---------------- prep: split x into bf16 hi/lo ----------------
__global__ void split_x_kernel(const float* __restrict__ x) {
    int i = (blockIdx.x * 256 + threadIdx.x) * 4;
    float4 v = *reinterpret_cast<const float4*>(x + i);
    __nv_bfloat162 h01 = __floats2bfloat162_rn(v.x, v.y);
    __nv_bfloat162 h23 = __floats2bfloat162_rn(v.z, v.w);
    __nv_bfloat162 l01 = __floats2bfloat162_rn(v.x - __bfloat162float(h01.x),
                                               v.y - __bfloat162float(h01.y));
    __nv_bfloat162 l23 = __floats2bfloat162_rn(v.z - __bfloat162float(h23.x),
                                               v.w - __bfloat162float(h23.y));
    *reinterpret_cast<__nv_bfloat162*>(g_xhi + i)     = h01;
    *reinterpret_cast<__nv_bfloat162*>(g_xhi + i + 2) = h23;
    *reinterpret_cast<__nv_bfloat162*>(g_xlo + i)     = l01;
    *reinterpret_cast<__nv_bfloat162*>(g_xlo + i + 2) = l23;
}

// ---------------- prep: W1||W3 transposed [e][n=128][k=512] bf16 hi/lo ----------------
__global__ __launch_bounds__(256) void split_w13_kernel(
    const float* __restrict__ w1, const float* __restrict__ w3)
{
    int e = blockIdx.x, kb = blockIdx.y;
    __shared__ float T1[64][65], T3[64][65];
    int tid = threadIdx.x;
    #pragma unroll
    for (int q = 0; q < 16; q++) {
        int idx = tid + q * 256;
        int kk = idx >> 6, j = idx & 63;
        size_t s = ((size_t)e * DIMX + kb * 64 + kk) * INTER + j;
        T1[kk][j] = w1[s];
        T3[kk][j] = w3[s];
    }
    __syncthreads();
    #pragma unroll
    for (int q = 0; q < 16; q++) {
        int idx = tid + q * 256;
        int j = idx >> 6, kk = idx & 63;
        float v1 = T1[kk][j], v3 = T3[kk][j];
        __nv_bfloat16 h1 = __float2bfloat16(v1);
        __nv_bfloat16 h3 = __float2bfloat16(v3);
        size_t o1 = ((size_t)e * 128 + j) * DIMX + kb * 64 + kk;
        size_t o3 = ((size_t)e * 128 + 64 + j) * DIMX + kb * 64 + kk;
        g_w13hi[o1] = h1;
        g_w13hi[o3] = h3;
        g_w13lo[o1] = __float2bfloat16(v1 - __bfloat162float(h1));
        g_w13lo[o3] = __float2bfloat16(v3 - __bfloat162float(h3));
    }
}

// ---------------- prep: W2 transposed [e][d=512][j=64] bf16 hi/lo ----------------
__global__ __launch_bounds__(256) void split_w2_kernel(const float* __restrict__ w2) {
    int e = blockIdx.x, db = blockIdx.y;
    __shared__ float T[64][65];
    int tid = threadIdx.x;
    #pragma unroll
    for (int q = 0; q < 16; q++) {
        int idx = tid + q * 256;
        int j = idx >> 6, d = idx & 63;
        T[j][d] = w2[((size_t)e * INTER + j) * DIMX + db * 64 + d];
    }
    __syncthreads();
    #pragma unroll
    for (int q = 0; q < 16; q++) {
        int idx = tid + q * 256;
        int d = idx >> 6, j = idx & 63;
        float v = T[j][d];
        __nv_bfloat16 h = __float2bfloat16(v);
        size_t o = ((size_t)e * DIMX + db * 64 + d) * INTER + j;
        g_w2hi[o] = h;
        g_w2lo[o] = __float2bfloat16(v - __bfloat162float(h));
    }
}

// ---------------- kernel 4: grouped expert FFN on mma.sync bf16 ----------------
// 128 threads (4 warps), tile = 32 tokens.
// SMEM tiles are [R][64] bf16, 128B rows, 16B-chunk XOR-by-row swizzle.
// h-stage: warp w owns W13 col slices [w*16, w*16+16) and [64+w*16, ...): paired h1/h3.
// W2-stage: warp w owns d slice [chunk*128 + w*32, +32).
__global__ __launch_bounds__(128, 2) void ffn_mma_kernel()
{
    extern __shared__ __align__(16) char dyn[];
    __shared__ int   toks[TILE_M];
    __shared__ float wts[TILE_M];
    __shared__ int   slots[TILE_M];

    int bid = blockIdx.x;
    if (bid >= g_ntiles) return;
    int4 tl = g_tiles[bid];
    int e = tl.x, p0 = tl.y, m = tl.z;

    int tid = threadIdx.x, wid = tid >> 5, lane = tid & 31;

    uint32_t sb = smem_u32(dyn);
    uint32_t Ah[2] = { sb,          sb + 4096  };
    uint32_t Al[2] = { sb + 8192,   sb + 12288 };
    uint32_t Bh[2] = { sb + 16384,  sb + 32768 };
    uint32_t Bl[2] = { sb + 49152,  sb + 65536 };
    uint32_t Gh = sb + 81920, Gl = sb + 86016;

    if (tid < TILE_M) {
        int i = (tid < m) ? g_perm[p0 + tid] : g_perm[p0];
        slots[tid] = i; toks[tid] = i >> 3; wts[tid] = g_wt[i];
    }
    __syncthreads();

    const __nv_bfloat16* w13h = g_w13hi + (size_t)e * 128 * DIMX;
    const __nv_bfloat16* w13l = g_w13lo + (size_t)e * 128 * DIMX;
    const __nv_bfloat16* w2h  = g_w2hi  + (size_t)e * DIMX * INTER;
    const __nv_bfloat16* w2l  = g_w2lo  + (size_t)e * DIMX * INTER;

    // ---- staging helpers (swizzled 16B chunks) ----
    auto stage_A = [&](const __nv_bfloat16* src, uint32_t dst, int kb) {
        #pragma unroll
        for (int q = 0; q < 2; q++) {
            int idx = tid + q * 128;          // 0..255
            int row = idx >> 3, c = idx & 7;
            cp16(dst + row * 128 + ((c ^ (row & 7)) << 4),
                 src + (size_t)toks[row] * DIMX + kb * 64 + c * 8);
        }
    };
    auto stage_B = [&](const __nv_bfloat16* src, uint32_t dst, int kb) {
        #pragma unroll
        for (int q = 0; q < 8; q++) {
            int idx = tid + q * 128;          // 0..1023
            int row = idx >> 3, c = idx & 7;
            cp16(dst + row * 128 + ((c ^ (row & 7)) << 4),
                 src + (size_t)row * DIMX + kb * 64 + c * 8);
        }
    };
    auto stage_W2 = [&](const __nv_bfloat16* src, uint32_t dst, int chunk) {
        #pragma unroll
        for (int q = 0; q < 8; q++) {
            int idx = tid + q * 128;
            int row = idx >> 3, c = idx & 7;
            cp16(dst + row * 128 + ((c ^ (row & 7)) << 4),
                 src + (size_t)(chunk * 128 + row) * INTER + c * 8);
        }
    };

    // ldmatrix address builders over a [R][64] swizzled tile
    auto addrA = [&](uint32_t base, int mt, int k0) {   // m16k16 frag, lanes all
        int row = mt * 16 + (lane & 15);
        int kc  = (k0 >> 3) + (lane >> 4);
        return base + row * 128 + (((uint32_t)kc ^ (row & 7)) << 4);
    };
    auto addrB = [&](uint32_t base, int nb, int k0) {   // n16k16 (2 n8 frags)
        int row = nb + (lane & 7) + ((lane >> 4) << 3);
        int kc  = (k0 >> 3) + ((lane >> 3) & 1);
        return base + row * 128 + (((uint32_t)kc ^ (row & 7)) << 4);
    };

    // ---- h-stage: acc[mt][nt]: nt 0,1 = h1 cols w*16+{0,8}; nt 2,3 = h3 ----
    float acc[2][4][4] = {};

    stage_A(g_xhi, Ah[0], 0); stage_A(g_xlo, Al[0], 0);
    stage_B(w13h, Bh[0], 0);  stage_B(w13l, Bl[0], 0);
    cp_commit();

    #pragma unroll 1
    for (int kb = 0; kb < 8; kb++) {
        int b = kb & 1;
        if (kb + 1 < 8) {
            int nb = b ^ 1;
            stage_A(g_xhi, Ah[nb], kb + 1); stage_A(g_xlo, Al[nb], kb + 1);
            stage_B(w13h, Bh[nb], kb + 1);  stage_B(w13l, Bl[nb], kb + 1);
            cp_commit();
            cp_wait<1>();
        } else {
            cp_wait<0>();
        }
        __syncthreads();

        #pragma unroll
        for (int pass = 0; pass < 3; pass++) {
            uint32_t Abase = (pass == 1) ? Al[b] : Ah[b];
            uint32_t Bbase = (pass == 2) ? Bl[b] : Bh[b];
            #pragma unroll
            for (int ks = 0; ks < 4; ks++) {
                int k0 = ks * 16;
                uint32_t a0[4], a1[4], bt[4][2];
                ldsm4(a0[0], a0[1], a0[2], a0[3], addrA(Abase, 0, k0));
                ldsm4(a1[0], a1[1], a1[2], a1[3], addrA(Abase, 1, k0));
                {
                    uint32_t r0, r1, r2, r3;
                    ldsm4(r0, r1, r2, r3, addrB(Bbase, wid * 16, k0));
                    bt[0][0] = r0; bt[0][1] = r1; bt[1][0] = r2; bt[1][1] = r3;
                    ldsm4(r0, r1, r2, r3, addrB(Bbase, 64 + wid * 16, k0));
                    bt[2][0] = r0; bt[2][1] = r1; bt[3][0] = r2; bt[3][1] = r3;
                }
                #pragma unroll
                for (int nt = 0; nt < 4; nt++) {
                    mma_bf16(acc[0][nt], a0, bt[nt]);
                    mma_bf16(acc[1][nt], a1, bt[nt]);
                }
            }
        }
        __syncthreads();
    }

    // prefetch W2 chunk 0 while epilogue runs
    stage_W2(w2h, Bh[0], 0); stage_W2(w2l, Bl[0], 0);
    cp_commit();

    // ---- epilogue: g = silu(h1)*h3 -> Gh/Gl [32][64] swizzled ----
    {
        int rbase = lane >> 2, cbase = (lane & 3) * 2;
        #pragma unroll
        for (int mt = 0; mt < 2; mt++) {
            #pragma unroll
            for (int p = 0; p < 2; p++) {
                const float* h1 = acc[mt][p];
                const float* h3 = acc[mt][p + 2];
                #pragma unroll
                for (int half = 0; half < 2; half++) {   // c0/c1 vs c2/c3 (row, row+8)
                    int row = mt * 16 + rbase + half * 8;
                    float v0 = h1[half * 2], v1 = h1[half * 2 + 1];
                    float g0 = v0 / (1.0f + __expf(-v0)) * h3[half * 2];
                    float g1 = v1 / (1.0f + __expf(-v1)) * h3[half * 2 + 1];
                    __nv_bfloat162 hh = __floats2bfloat162_rn(g0, g1);
                    __nv_bfloat162 ll = __floats2bfloat162_rn(g0 - __bfloat162float(hh.x),
                                                              g1 - __bfloat162float(hh.y));
                    int j = wid * 16 + p * 8 + cbase;
                    uint32_t off = row * 128 + (((uint32_t)(j >> 3) ^ (row & 7)) << 4)
                                   + (j & 7) * 2;
                    *reinterpret_cast<__nv_bfloat162*>(
                        (char*)dyn + (Gh - sb) + off) = hh;
                    *reinterpret_cast<__nv_bfloat162*>(
                        (char*)dyn + (Gl - sb) + off) = ll;
                }
            }
        }
    }
    __syncthreads();

    // ---- W2 stage: 4 chunks of 128 d; K = 64 j, 3 passes ----
    int rbase = lane >> 2, cbase = (lane & 3) * 2;
    #pragma unroll 1
    for (int c = 0; c < 4; c++) {
        int b = c & 1;
        if (c + 1 < 4) {
            int nb = b ^ 1;
            stage_W2(w2h, Bh[nb], c + 1); stage_W2(w2l, Bl[nb], c + 1);
            cp_commit();
            cp_wait<1>();
        } else {
            cp_wait<0>();
        }
        __syncthreads();

        float oacc[2][4][4] = {};
        #pragma unroll
        for (int pass = 0; pass < 3; pass++) {
            uint32_t Abase = (pass == 1) ? Gl : Gh;
            uint32_t Bbase = (pass == 2) ? Bl[b] : Bh[b];
            #pragma unroll
            for (int ks = 0; ks < 4; ks++) {
                int k0 = ks * 16;
                uint32_t a0[4], a1[4], bt[4][2];
                ldsm4(a0[0], a0[1], a0[2], a0[3], addrA(Abase, 0, k0));
                ldsm4(a1[0], a1[1], a1[2], a1[3], addrA(Abase, 1, k0));
                {
                    uint32_t r0, r1, r2, r3;
                    ldsm4(r0, r1, r2, r3, addrB(Bbase, wid * 32, k0));
                    bt[0][0] = r0; bt[0][1] = r1; bt[1][0] = r2; bt[1][1] = r3;
                    ldsm4(r0, r1, r2, r3, addrB(Bbase, wid * 32 + 16, k0));
                    bt[2][0] = r0; bt[2][1] = r1; bt[3][0] = r2; bt[3][1] = r3;
                }
                #pragma unroll
                for (int nt = 0; nt < 4; nt++) {
                    mma_bf16(oacc[0][nt], a0, bt[nt]);
                    mma_bf16(oacc[1][nt], a1, bt[nt]);
                }
            }
        }
        // write weighted outputs
        #pragma unroll
        for (int mt = 0; mt < 2; mt++) {
            #pragma unroll
            for (int half = 0; half < 2; half++) {
                int r = mt * 16 + rbase + half * 8;
                if (r < m) {
                    float wt = wts[r];
                    float* orow = g_slot_out + (size_t)slots[r] * DIMX;
                    #pragma unroll
                    for (int nt = 0; nt < 4; nt++) {
                        int col = c * 128 + wid * 32 + nt * 8 + cbase;
                        float2 v;
                        v.x = oacc[mt][nt][half * 2]     * wt;
                        v.y = oacc[mt][nt][half * 2 + 1] * wt;
                        *reinterpret_cast<float2*>(orow + col) = v;
                    }
                }
            }
        }
        __syncthreads();
    }
}

// ---------------- kernel 5: combine ----------------
__global__ void combine_kernel(float* __restrict__ out) {
    int i = blockIdx.x * 256 + threadIdx.x;
    if (i >= NTOK * DIMX / 4) return;
    int t = i >> 7;
    int d4 = i & (DIMX/4 - 1);
    float4 s = make_float4(0.f, 0.f, 0.f, 0.f);
    #pragma unroll
    for (int sl = 0; sl < KSLOT; sl++) {
        const float4* p = reinterpret_cast<const float4*>(
            &g_slot_out[((size_t)(t * KSLOT + sl)) * DIMX]);
        float4 v = p[d4];
        s.x += v.x; s.y += v.y; s.z += v.z; s.w += v.w;
    }
    reinterpret_cast<float4*>(out)[i] = s;
}

// ---------------- launch ----------------
extern "C" void kernel_launch(void* const* d_in, const int* in_sizes, int n_in,
                              void* d_out, int out_size) {
    const float* x  = (const float*)d_in[0];
    const float* gw = (const float*)d_in[1];
    const float* gb = (const float*)d_in[2];
    const float* w1 = (const float*)d_in[3];
    const float* w2 = (const float*)d_in[4];
    const float* w3 = (const float*)d_in[5];
    float* out = (float*)d_out;

    const int ffn_smem = 90112;   // A 16K + B 64K + G 8K + pad
    cudaFuncSetAttribute(ffn_mma_kernel,
                         cudaFuncAttributeMaxDynamicSharedMemorySize, ffn_smem);

    zero_kernel<<<1, 128>>>();
    gate_kernel<<<NTOK / 32, 256>>>(x, gw, gb);
    scan_kernel<<<1, 128>>>();
    scatter_kernel<<<NSLOT / 256, 256>>>();
    split_x_kernel<<<NTOK * DIMX / (256 * 4), 256>>>(x);
    split_w13_kernel<<<dim3(NEXP, DIMX / 64), 256>>>(w1, w3);
    split_w2_kernel<<<dim3(NEXP, DIMX / 64), 256>>>(w2);
    ffn_mma_kernel<<<MAXTILES, 128, ffn_smem>>>();
    combine_kernel<<<(NTOK * DIMX / 4) / 256, 256>>>(out);
}